// round 5
// baseline (speedup 1.0000x reference)
#include <cuda_runtime.h>
#include <cstdint>

#define NB 32
#define NP 64
#define NV 32000
#define NROWS (NB * NP)
#define NUNITS (NROWS * 2)     // half-row work units
#define HALFV (NV / 2)         // 16000 floats per unit
#define GRID_X 1216            // 152 SMs * 8 blocks/SM, true single wave

// scratch (no allocations allowed)
__device__ double g_half[NUNITS];   // per half-row sum
__device__ float  g_sumS[NROWS];
__device__ int    g_m[NROWS];
__device__ int    g_ctr    = 0;     // work-stealing unit counter
__device__ int    g_ticket = 0;     // last-block ticket

__global__ void __launch_bounds__(256, 8) fused_kernel(
    const float* __restrict__ outputs,
    const int*   __restrict__ outsym,
    const int*   __restrict__ targets,
    const unsigned char* __restrict__ mask,
    float* __restrict__ out)
{
    const int tid = threadIdx.x;
    const int wid = tid >> 5;
    const int l   = tid & 31;

    __shared__ int                s_unit;
    __shared__ double             red[8];
    __shared__ int                last_sh;
    __shared__ int                tgt_s[64];
    __shared__ unsigned long long vp_s[64], vn_s[64];
    __shared__ unsigned long long mm_sh;

    // =====================================================================
    // Blocks 0..31: per-batch DP (once per batch, all 8 warps used).
    // =====================================================================
    if (blockIdx.x < NB) {
        const int b = blockIdx.x;

        if (wid == 0) {
            const int t_lo = targets[b * 64 + l];
            const int t_hi = targets[b * 64 + 32 + l];
            tgt_s[l]      = t_lo;
            tgt_s[32 + l] = t_hi;
            const int sym = outsym[b * 64 + l];         // lane l = symbol l
            const int symh= outsym[b * 64 + 32 + l];
            const unsigned mml = __ballot_sync(0xffffffffu, mask[b * 64 + l] != 0);
            const unsigned mmh = __ballot_sync(0xffffffffu, mask[b * 64 + 32 + l] != 0);
            if (l == 0)
                mm_sh = ((unsigned long long)mmh << 32) | (unsigned long long)mml;

            // Myers bit-vector DP; snapshot every row's (VP, VN).
            unsigned long long VP = 0x7FFFFFFFFFFFFFFFull;  // row 0 = arange
            unsigned long long VN = 0ull;
            vp_s[0] = VP; vn_s[0] = VN;
            for (int i = 1; i < 64; i++) {
                const int s = (i - 1 < 32) ? __shfl_sync(0xffffffffu, sym,  i - 1)
                                           : __shfl_sync(0xffffffffu, symh, i - 33);
                const unsigned eql = __ballot_sync(0xffffffffu, t_lo == s);
                const unsigned eqh = __ballot_sync(0xffffffffu, t_hi == s) & 0x7FFFFFFFu;
                const unsigned long long Eq =
                    ((unsigned long long)eqh << 32) | (unsigned long long)eql;
                const unsigned long long X  = Eq | VN;
                const unsigned long long D0 = ((VP + (X & VP)) ^ VP) | X;
                const unsigned long long HN = VP & D0;
                const unsigned long long HP = VN | ~(VP | D0);
                const unsigned long long X2 = (HP << 1) | 1ull;
                VN = X2 & D0;
                VP = (HN << 1) | ~(X2 | D0);
                vp_s[i] = VP; vn_s[i] = VN;
            }
        }
        __syncthreads();

        // All 8 warps: analyze 8 rows each (warp-parallel per row).
        const unsigned long long mm = mm_sh;
        const int t_lo = tgt_s[l];
        const int t_hi = tgt_s[32 + l];
        const unsigned long long lm0 = (1ull << l) - 1ull;
        const unsigned long long lm1 = (1ull << (l + 32)) - 1ull;

        for (int rr = 0; rr < 8; rr++) {
            const int r = wid * 8 + rr;
            if (!((mm >> r) & 1ull)) continue;     // masked row: loss is 0

            const unsigned long long vp = vp_s[r];
            const unsigned long long vn = vn_s[r];
            const int d0 = r + __popcll(vp & lm0) - __popcll(vn & lm0);
            const int d1 = r + __popcll(vp & lm1) - __popcll(vn & lm1);
            const int md0 = ((mm >> l) & 1ull)        ? d0 : 0x7fffffff;
            const int md1 = ((mm >> (l + 32)) & 1ull) ? d1 : 0x7fffffff;

            int mn = min(md0, md1);
            #pragma unroll
            for (int o = 16; o > 0; o >>= 1)
                mn = min(mn, __shfl_xor_sync(0xffffffffu, mn, o));

            const unsigned cm_lo = __ballot_sync(0xffffffffu, md0 == mn);
            const unsigned cm_hi = __ballot_sync(0xffffffffu, md1 == mn);
            const unsigned long long CM =
                ((unsigned long long)cm_hi << 32) | (unsigned long long)cm_lo;

            // dedup: keep col c iff no earlier argmin col has same vocab id
            bool keep0 = (md0 == mn);
            if (keep0) {
                unsigned long long e = CM & lm0;
                while (e) {
                    const int c = __ffsll((long long)e) - 1;
                    e &= e - 1;
                    if (tgt_s[c] == t_lo) { keep0 = false; break; }
                }
            }
            bool keep1 = (md1 == mn);
            if (keep1) {
                unsigned long long e = CM & lm1;
                while (e) {
                    const int c = __ffsll((long long)e) - 1;
                    e &= e - 1;
                    if (tgt_s[c] == t_hi) { keep1 = false; break; }
                }
            }
            const unsigned k0 = __ballot_sync(0xffffffffu, keep0);
            const unsigned k1 = __ballot_sync(0xffffffffu, keep1);
            const int m = __popc(k0) + __popc(k1);

            const float* rowp = outputs + (size_t)(b * 64 + r) * NV;
            float s = 0.f;
            if (keep0) s += __ldg(rowp + t_lo);
            if (keep1) s += __ldg(rowp + t_hi);
            #pragma unroll
            for (int o = 16; o > 0; o >>= 1)
                s += __shfl_xor_sync(0xffffffffu, s, o);

            if (l == 0) { g_m[b * 64 + r] = m; g_sumS[b * 64 + r] = s; }
        }
        __syncthreads();
    }

    // =====================================================================
    // Streaming: all 8 warps sum half-rows pulled from the steal counter.
    // =====================================================================
    for (;;) {
        if (tid == 0) s_unit = atomicAdd(&g_ctr, 1);
        __syncthreads();
        const int u = s_unit;
        if (u >= NUNITS) break;

        const int row = u >> 1;
        if (mask[row]) {
            const float4* p =
                (const float4*)(outputs + (size_t)row * NV + (u & 1) * HALFV);
            float s = 0.f, comp = 0.f;
            #pragma unroll 8
            for (int i = tid; i < HALFV / 4; i += 256) {
                const float4 v = p[i];
                const float t = (v.x + v.y) + (v.z + v.w);
                const float y = t - comp;
                const float uu = s + y;
                comp = (uu - s) - y;
                s = uu;
            }
            double ds = (double)s - (double)comp;
            #pragma unroll
            for (int o = 16; o > 0; o >>= 1)
                ds += __shfl_xor_sync(0xffffffffu, ds, o);
            if (l == 0) red[wid] = ds;
            __syncthreads();
            if (tid == 0) {
                double t = 0.0;
                #pragma unroll
                for (int w = 0; w < 8; w++) t += red[w];
                g_half[u] = t;
            }
        }
        __syncthreads();   // protect s_unit / red reuse
    }

    // =====================================================================
    // Last block: per-row closed-form loss + hierarchical reduction.
    // =====================================================================
    if (tid == 0) {
        __threadfence();
        last_sh = (atomicAdd(&g_ticket, 1) == GRID_X - 1);
    }
    __syncthreads();

    if (last_sh) {
        __shared__ double logD_tab[65];
        __shared__ double pb_sh[32];
        __shared__ int    ne_sh[32];

        const double einv = 0.36787944117144233;       // e^-1
        if (tid < 65)
            logD_tab[tid] = log((double)tid + (double)(NV - tid) * einv);
        __syncthreads();

        // thread t: batch bb = t>>3, chunk sub = t&7 (8 rows each)
        const int bb  = tid >> 3;
        const int sub = tid & 7;
        double ls = 0.0, w = 0.0;
        #pragma unroll
        for (int j = 0; j < 8; j++) {
            const int idx = bb * 64 + sub * 8 + j;
            if (mask[idx]) {
                const double tot  = g_half[2 * idx] + g_half[2 * idx + 1];
                const int    m    = g_m[idx];
                const double sumS = (double)g_sumS[idx];
                const double D    = (double)m + (double)(NV - m) * einv;
                const double phi  = 1.0 / D;
                const double plo  = einv / D;
                // kl = -log D - (V-m)*plo - plo*tot - (phi-plo)*sumS
                ls += -logD_tab[m] - (double)(NV - m) * plo
                      - plo * tot - (phi - plo) * sumS;
                w  += 1.0;
            }
        }
        #pragma unroll
        for (int o = 4; o > 0; o >>= 1) {
            ls += __shfl_xor_sync(0xffffffffu, ls, o);
            w  += __shfl_xor_sync(0xffffffffu, w,  o);
        }
        if (sub == 0) {
            pb_sh[bb] = ls / (w + 1e-13);
            ne_sh[bb] = (w > 0.0) ? 1 : 0;
        }
        __syncthreads();

        if (tid < 32) {
            double pb = pb_sh[tid];
            int    ne = ne_sh[tid];
            #pragma unroll
            for (int o = 16; o > 0; o >>= 1) {
                pb += __shfl_xor_sync(0xffffffffu, pb, o);
                ne += __shfl_xor_sync(0xffffffffu, ne, o);
            }
            if (tid == 0) {
                out[0] = (float)(pb / ((double)ne + 1e-13));
                g_ticket = 0;          // reset for next graph replay
                g_ctr    = 0;
            }
        }
    }
}

extern "C" void kernel_launch(void* const* d_in, const int* in_sizes, int n_in,
                              void* d_out, int out_size)
{
    const float* outputs        = (const float*)d_in[0];
    const int*   output_symbols = (const int*)d_in[1];
    const int*   targets        = (const int*)d_in[2];
    const unsigned char* mask   = (const unsigned char*)d_in[3];

    fused_kernel<<<GRID_X, 256>>>(outputs, output_symbols, targets, mask,
                                  (float*)d_out);
}